// round 2
// baseline (speedup 1.0000x reference)
#include <cuda_runtime.h>
#include <cstdint>
#include <cstddef>

#define BSZ    4
#define GRID_S 64
#define DIM    1024
#define NHEAD  16
#define DHEAD  64
#define NTOK   4096
#define ROWS   (BSZ*NTOK)

// ---------------- scratch ----------------
__device__ __align__(256) float g_norm[(size_t)ROWS*DIM];
__device__ __align__(256) float g_qkv [(size_t)ROWS*3*DIM];
__device__ __align__(256) float g_attn[(size_t)ROWS*DIM];
__device__ __align__(256) float g_res [(size_t)ROWS*DIM];
__device__ __align__(256) float g_out1[(size_t)ROWS*DIM];
__device__ __align__(256) float g_hid [(size_t)ROWS*4*DIM];

// ---------------- LayerNorm ----------------
__global__ __launch_bounds__(256) void ln_kernel(const float* __restrict__ x,
                                                 const float* __restrict__ g,
                                                 const float* __restrict__ b,
                                                 float* __restrict__ y)
{
    int row = blockIdx.x, t = threadIdx.x;
    float4 v = reinterpret_cast<const float4*>(x + (size_t)row * DIM)[t];
    float s = v.x + v.y + v.z + v.w;
    float q = v.x*v.x + v.y*v.y + v.z*v.z + v.w*v.w;
    #pragma unroll
    for (int o = 16; o > 0; o >>= 1) {
        s += __shfl_xor_sync(0xffffffffu, s, o);
        q += __shfl_xor_sync(0xffffffffu, q, o);
    }
    __shared__ float rs_[8], rq_[8];
    __shared__ float s_mu, s_rs;
    if ((t & 31) == 0) { rs_[t>>5] = s; rq_[t>>5] = q; }
    __syncthreads();
    if (t == 0) {
        float S = 0.f, Q = 0.f;
        #pragma unroll
        for (int i = 0; i < 8; i++) { S += rs_[i]; Q += rq_[i]; }
        float mu = S * (1.0f/DIM);
        s_mu = mu;
        s_rs = rsqrtf(Q * (1.0f/DIM) - mu*mu + 1e-5f);
    }
    __syncthreads();
    float mu = s_mu, r = s_rs;
    float4 g4 = reinterpret_cast<const float4*>(g)[t];
    float4 b4 = reinterpret_cast<const float4*>(b)[t];
    float4 o;
    o.x = (v.x-mu)*r*g4.x + b4.x;  o.y = (v.y-mu)*r*g4.y + b4.y;
    o.z = (v.z-mu)*r*g4.z + b4.z;  o.w = (v.w-mu)*r*g4.w + b4.w;
    reinterpret_cast<float4*>(y + (size_t)row * DIM)[t] = o;
}

// ---------------- TF32 GEMM: C = A@B + bias (+Rsd) ----------------
#define GBM 128
#define GBN 128
#define GBK 32
#define LDSP 36
#define GEMM_SMEM (2*(GBM*LDSP + GBN*LDSP)*4)

__device__ __forceinline__ uint32_t f2tf(float f) {
    uint32_t r; asm("cvt.rna.tf32.f32 %0, %1;" : "=r"(r) : "f"(f)); return r;
}
__device__ __forceinline__ void ldsm4(uint32_t& r0, uint32_t& r1, uint32_t& r2, uint32_t& r3, uint32_t a) {
    asm volatile("ldmatrix.sync.aligned.m8n8.x4.shared.b16 {%0,%1,%2,%3}, [%4];"
                 : "=r"(r0), "=r"(r1), "=r"(r2), "=r"(r3) : "r"(a));
}
__device__ __forceinline__ void mma_tf32(float* c, const uint32_t* a, const uint32_t* b) {
    asm volatile("mma.sync.aligned.m16n8k8.row.col.f32.tf32.tf32.f32 "
                 "{%0,%1,%2,%3}, {%4,%5,%6,%7}, {%8,%9}, {%0,%1,%2,%3};"
                 : "+f"(c[0]), "+f"(c[1]), "+f"(c[2]), "+f"(c[3])
                 : "r"(a[0]), "r"(a[1]), "r"(a[2]), "r"(a[3]), "r"(b[0]), "r"(b[1]));
}

template <bool RES>
__global__ __launch_bounds__(256, 1) void gemm_tf32(
    const float* __restrict__ A, const float* __restrict__ B,
    const float* __restrict__ bias, const float* __restrict__ Rsd,
    float* __restrict__ C, int M, int N, int K)
{
    extern __shared__ float smem[];
    float* As = smem;
    float* Bs = smem + 2 * GBM * LDSP;

    const int t = threadIdx.x, lane = t & 31, warp = t >> 5;
    const int wm = warp >> 2, wn = warp & 3;
    const int bm0 = blockIdx.y * GBM, bn0 = blockIdx.x * GBN;

    const int arow = t >> 3, acol4 = t & 7;
    const int bn = t & 127, bk0 = (t >> 7) * 16;

    const float* Ag = A + (size_t)(bm0 + arow) * K + acol4 * 4;
    const float* Bg = B + (size_t)bk0 * N + bn0 + bn;

    const int lrow = (lane & 7) + ((lane >> 3) & 1) * 8;
    const int lcol = ((lane >> 4) & 1) * 4;
    const uint32_t as_u = (uint32_t)__cvta_generic_to_shared(As);
    const uint32_t bs_u = (uint32_t)__cvta_generic_to_shared(Bs);
    const uint32_t a_off = ((wm*64 + lrow) * LDSP + lcol) * 4;
    const uint32_t b_off = ((wn*32 + lrow) * LDSP + lcol) * 4;

    float4 ra[4];
    float  rb[16];
    float  acc[4][4][4];
    #pragma unroll
    for (int i = 0; i < 4; i++)
        #pragma unroll
        for (int j = 0; j < 4; j++)
            #pragma unroll
            for (int k = 0; k < 4; k++) acc[i][j][k] = 0.f;

    auto gload = [&](int kt) {
        #pragma unroll
        for (int s = 0; s < 4; s++)
            ra[s] = *reinterpret_cast<const float4*>(Ag + (size_t)s * 32 * K + (size_t)kt * GBK);
        #pragma unroll
        for (int s = 0; s < 16; s++)
            rb[s] = Bg[(size_t)(kt * GBK + s) * N];
    };
    auto sstore = [&](int st) {
        float* Ad = As + st * GBM * LDSP;
        #pragma unroll
        for (int s = 0; s < 4; s++) {
            uint32_t u[4] = { f2tf(ra[s].x), f2tf(ra[s].y), f2tf(ra[s].z), f2tf(ra[s].w) };
            *reinterpret_cast<uint4*>(&Ad[(arow + s*32) * LDSP + acol4*4]) = *reinterpret_cast<uint4*>(u);
        }
        float* Bd = Bs + st * GBN * LDSP;
        #pragma unroll
        for (int s4 = 0; s4 < 4; s4++) {
            uint32_t u[4] = { f2tf(rb[s4*4+0]), f2tf(rb[s4*4+1]), f2tf(rb[s4*4+2]), f2tf(rb[s4*4+3]) };
            *reinterpret_cast<uint4*>(&Bd[bn * LDSP + bk0 + s4*4]) = *reinterpret_cast<uint4*>(u);
        }
    };
    auto compute = [&](int st) {
        uint32_t ab = as_u + (uint32_t)st * GBM * LDSP * 4 + a_off;
        uint32_t bb = bs_u + (uint32_t)st * GBN * LDSP * 4 + b_off;
        #pragma unroll
        for (int kk = 0; kk < 4; kk++) {
            uint32_t afr[4][4];
            #pragma unroll
            for (int ms = 0; ms < 4; ms++)
                ldsm4(afr[ms][0], afr[ms][1], afr[ms][2], afr[ms][3],
                      ab + (uint32_t)(ms*16*LDSP + kk*8) * 4);
            uint32_t bfr[4][2];
            #pragma unroll
            for (int p = 0; p < 2; p++) {
                uint32_t r0, r1, r2, r3;
                ldsm4(r0, r1, r2, r3, bb + (uint32_t)(p*16*LDSP + kk*8) * 4);
                bfr[2*p][0] = r0; bfr[2*p][1] = r2;
                bfr[2*p+1][0] = r1; bfr[2*p+1][1] = r3;
            }
            #pragma unroll
            for (int ms = 0; ms < 4; ms++)
                #pragma unroll
                for (int nt = 0; nt < 4; nt++)
                    mma_tf32(acc[ms][nt], afr[ms], bfr[nt]);
        }
    };

    const int KT = K / GBK;
    gload(0);
    sstore(0);
    __syncthreads();
    for (int kt = 0; kt < KT; kt++) {
        if (kt + 1 < KT) gload(kt + 1);
        compute(kt & 1);
        if (kt + 1 < KT) { sstore((kt + 1) & 1); __syncthreads(); }
    }

    #pragma unroll
    for (int ms = 0; ms < 4; ms++) {
        int r0 = bm0 + wm*64 + ms*16 + (lane >> 2);
        #pragma unroll
        for (int nt = 0; nt < 4; nt++) {
            int c0 = bn0 + wn*32 + nt*8 + (lane & 3)*2;
            float2 bv = *reinterpret_cast<const float2*>(&bias[c0]);
            float2 o0, o1;
            o0.x = acc[ms][nt][0] + bv.x;  o0.y = acc[ms][nt][1] + bv.y;
            o1.x = acc[ms][nt][2] + bv.x;  o1.y = acc[ms][nt][3] + bv.y;
            if (RES) {
                float2 v0 = *reinterpret_cast<const float2*>(&Rsd[(size_t)r0 * N + c0]);
                float2 v1 = *reinterpret_cast<const float2*>(&Rsd[(size_t)(r0+8) * N + c0]);
                o0.x += v0.x; o0.y += v0.y;  o1.x += v1.x; o1.y += v1.y;
            }
            *reinterpret_cast<float2*>(&C[(size_t)r0 * N + c0]) = o0;
            *reinterpret_cast<float2*>(&C[(size_t)(r0+8) * N + c0]) = o1;
        }
    }
}

// ---------------- window attention ----------------
#define APAD 68
#define ATTN_SMEM (4*64*APAD*4)

template <bool SHIFTED>
__global__ __launch_bounds__(256) void attn_kernel(const float* __restrict__ qkv,
                                                   float* __restrict__ out)
{
    extern __shared__ float sm[];
    float* Qst = sm;                  // [d][l]
    float* Kst = Qst + 64*APAD;       // [d][l]
    float* Vs  = Kst + 64*APAD;       // [l][d]
    float* Pt  = Vs  + 64*APAD;       // [j][i]
    __shared__ int tok[64];
    __shared__ int rid[64];

    const int h  = blockIdx.x;
    const int wb = blockIdx.y;
    const int t  = threadIdx.x;
    const int b = wb >> 6, win = wb & 63;
    const int wr = win >> 3, wc = win & 7;

    if (t < 64) {
        int r = wr*8 + (t >> 3), c = wc*8 + (t & 7);
        int rr = r, cc = c;
        if (SHIFTED) { rr = (r + 4) & 63; cc = (c + 4) & 63; }
        tok[t] = b * NTOK + rr * GRID_S + cc;
        if (SHIFTED) {
            int fr = (r < 56) ? 0 : ((r < 60) ? 1 : 2);
            int fc = (c < 56) ? 0 : ((c < 60) ? 1 : 2);
            rid[t] = fr * 3 + fc;
        }
    }
    __syncthreads();

    {
        int l = t >> 2, d0 = (t & 3) * 16;
        const float* bp = qkv + (size_t)tok[l] * (3*DIM) + h * DHEAD;
        #pragma unroll
        for (int u = 0; u < 4; u++) {
            int d = d0 + u*4;
            float4 q4 = *reinterpret_cast<const float4*>(bp + d);
            float4 k4 = *reinterpret_cast<const float4*>(bp + DIM + d);
            float4 v4 = *reinterpret_cast<const float4*>(bp + 2*DIM + d);
            Qst[(d+0)*APAD + l] = q4.x; Qst[(d+1)*APAD + l] = q4.y;
            Qst[(d+2)*APAD + l] = q4.z; Qst[(d+3)*APAD + l] = q4.w;
            Kst[(d+0)*APAD + l] = k4.x; Kst[(d+1)*APAD + l] = k4.y;
            Kst[(d+2)*APAD + l] = k4.z; Kst[(d+3)*APAD + l] = k4.w;
            *reinterpret_cast<float4*>(&Vs[l*APAD + d]) = v4;
        }
    }
    __syncthreads();

    // scores -> Pt[j][i]
    {
        int i0 = (t >> 4) * 4, j0 = (t & 15) * 4;
        float a[4][4];
        #pragma unroll
        for (int i = 0; i < 4; i++)
            #pragma unroll
            for (int j = 0; j < 4; j++) a[i][j] = 0.f;
        #pragma unroll 8
        for (int d = 0; d < 64; d++) {
            float4 qv = *reinterpret_cast<const float4*>(&Qst[d*APAD + i0]);
            float4 kv = *reinterpret_cast<const float4*>(&Kst[d*APAD + j0]);
            float qa[4] = { qv.x, qv.y, qv.z, qv.w };
            float ka[4] = { kv.x, kv.y, kv.z, kv.w };
            #pragma unroll
            for (int i = 0; i < 4; i++)
                #pragma unroll
                for (int j = 0; j < 4; j++)
                    a[i][j] = fmaf(qa[i], ka[j], a[i][j]);
        }
        #pragma unroll
        for (int jj = 0; jj < 4; jj++) {
            float4 o;
            float* op = &o.x;
            #pragma unroll
            for (int ii = 0; ii < 4; ii++) {
                float s = a[ii][jj] * 0.125f;
                if (SHIFTED && (rid[i0+ii] != rid[j0+jj])) s = -1e9f;
                op[ii] = s;
            }
            *reinterpret_cast<float4*>(&Pt[(j0+jj)*APAD + i0]) = o;
        }
    }
    __syncthreads();

    // softmax over j for row i (Pt column i)
    if (t < 64) {
        float m = -1e30f;
        #pragma unroll 8
        for (int j = 0; j < 64; j++) m = fmaxf(m, Pt[j*APAD + t]);
        float s = 0.f;
        #pragma unroll 8
        for (int j = 0; j < 64; j++) {
            float e = __expf(Pt[j*APAD + t] - m);
            Pt[j*APAD + t] = e;
            s += e;
        }
        float inv = 1.0f / s;
        #pragma unroll 8
        for (int j = 0; j < 64; j++) Pt[j*APAD + t] *= inv;
    }
    __syncthreads();

    // out[i][d] = sum_j P[i][j] V[j][d]
    {
        int i0 = (t >> 4) * 4, d0 = (t & 15) * 4;
        float a[4][4];
        #pragma unroll
        for (int i = 0; i < 4; i++)
            #pragma unroll
            for (int d = 0; d < 4; d++) a[i][d] = 0.f;
        #pragma unroll 8
        for (int j = 0; j < 64; j++) {
            float4 pv = *reinterpret_cast<const float4*>(&Pt[j*APAD + i0]);
            float4 vv = *reinterpret_cast<const float4*>(&Vs[j*APAD + d0]);
            float pa[4] = { pv.x, pv.y, pv.z, pv.w };
            float va[4] = { vv.x, vv.y, vv.z, vv.w };
            #pragma unroll
            for (int i = 0; i < 4; i++)
                #pragma unroll
                for (int d = 0; d < 4; d++)
                    a[i][d] = fmaf(pa[i], va[d], a[i][d]);
        }
        #pragma unroll
        for (int ii = 0; ii < 4; ii++) {
            float4 o = { a[ii][0], a[ii][1], a[ii][2], a[ii][3] };
            *reinterpret_cast<float4*>(&out[(size_t)tok[i0+ii]*DIM + h*DHEAD + d0]) = o;
        }
    }
}

// ---------------- host launch ----------------
static void run_gemm(const float* A, const float* B, const float* bias,
                     const float* Rsd, float* C, int M, int N, int K)
{
    dim3 grid(N / GBN, M / GBM);
    if (Rsd) {
        cudaFuncSetAttribute(gemm_tf32<true>, cudaFuncAttributeMaxDynamicSharedMemorySize, GEMM_SMEM);
        gemm_tf32<true><<<grid, 256, GEMM_SMEM>>>(A, B, bias, Rsd, C, M, N, K);
    } else {
        cudaFuncSetAttribute(gemm_tf32<false>, cudaFuncAttributeMaxDynamicSharedMemorySize, GEMM_SMEM);
        gemm_tf32<false><<<grid, 256, GEMM_SMEM>>>(A, B, bias, nullptr, C, M, N, K);
    }
}

extern "C" void kernel_launch(void* const* d_in, const int* in_sizes, int n_in,
                              void* d_out, int out_size)
{
    const float* x      = (const float*)d_in[0];
    const float* ln1g   = (const float*)d_in[1];
    const float* ln1b   = (const float*)d_in[2];
    const float* ln2g   = (const float*)d_in[3];
    const float* ln2b   = (const float*)d_in[4];
    const float* ln3g   = (const float*)d_in[5];
    const float* ln3b   = (const float*)d_in[6];
    const float* ln4g   = (const float*)d_in[7];
    const float* ln4b   = (const float*)d_in[8];
    const float* m1aw   = (const float*)d_in[9];
    const float* m1ab   = (const float*)d_in[10];
    const float* m2aw   = (const float*)d_in[11];
    const float* m2ab   = (const float*)d_in[12];
    const float* m1bw   = (const float*)d_in[13];
    const float* m1bb   = (const float*)d_in[14];
    const float* m2bw   = (const float*)d_in[15];
    const float* m2bb   = (const float*)d_in[16];
    const float* a1qkvw = (const float*)d_in[17];
    const float* a1qkvb = (const float*)d_in[18];
    const float* a1ow   = (const float*)d_in[19];
    const float* a1ob   = (const float*)d_in[20];
    const float* a2qkvw = (const float*)d_in[21];
    const float* a2qkvb = (const float*)d_in[22];
    const float* a2ow   = (const float*)d_in[23];
    const float* a2ob   = (const float*)d_in[24];
    float* out = (float*)d_out;

    float *nrm, *qkv, *att, *res, *out1, *hid;
    cudaGetSymbolAddress((void**)&nrm,  g_norm);
    cudaGetSymbolAddress((void**)&qkv,  g_qkv);
    cudaGetSymbolAddress((void**)&att,  g_attn);
    cudaGetSymbolAddress((void**)&res,  g_res);
    cudaGetSymbolAddress((void**)&out1, g_out1);
    cudaGetSymbolAddress((void**)&hid,  g_hid);

    cudaFuncSetAttribute(attn_kernel<false>, cudaFuncAttributeMaxDynamicSharedMemorySize, ATTN_SMEM);
    cudaFuncSetAttribute(attn_kernel<true>,  cudaFuncAttributeMaxDynamicSharedMemorySize, ATTN_SMEM);

    // ---- layer 1: W-MSA ----
    ln_kernel<<<ROWS, 256>>>(x, ln1g, ln1b, nrm);
    run_gemm(nrm, a1qkvw, a1qkvb, nullptr, qkv, ROWS, 3*DIM, DIM);
    attn_kernel<false><<<dim3(NHEAD, BSZ*64), 256, ATTN_SMEM>>>(qkv, att);
    run_gemm(att, a1ow, a1ob, nrm, res, ROWS, DIM, DIM);        // w = inp1 + attn@Wo
    // ---- layer 1: MLP ----
    ln_kernel<<<ROWS, 256>>>(res, ln2g, ln2b, nrm);
    run_gemm(nrm, m1aw, m1ab, nullptr, hid, ROWS, 4*DIM, DIM);
    run_gemm(hid, m1bw, m1bb, res, out1, ROWS, DIM, 4*DIM);
    // ---- layer 2: SW-MSA ----
    ln_kernel<<<ROWS, 256>>>(out1, ln3g, ln3b, nrm);
    run_gemm(nrm, a2qkvw, a2qkvb, nullptr, qkv, ROWS, 3*DIM, DIM);
    attn_kernel<true><<<dim3(NHEAD, BSZ*64), 256, ATTN_SMEM>>>(qkv, att);
    run_gemm(att, a2ow, a2ob, out1, res, ROWS, DIM, DIM);       // sw = out1 + attn@Wo
    // ---- layer 2: MLP ----
    ln_kernel<<<ROWS, 256>>>(res, ln4g, ln4b, nrm);
    run_gemm(nrm, m2aw, m2ab, nullptr, hid, ROWS, 4*DIM, DIM);
    run_gemm(hid, m2bw, m2bb, res, out, ROWS, DIM, 4*DIM);
}

// round 3
// speedup vs baseline: 1.1518x; 1.1518x over previous
#include <cuda_runtime.h>
#include <cstdint>
#include <cstddef>

#define BSZ    4
#define GRID_S 64
#define DIM    1024
#define NHEAD  16
#define DHEAD  64
#define NTOK   4096
#define ROWS   (BSZ*NTOK)

// ---------------- scratch ----------------
__device__ __align__(256) float g_norm[(size_t)ROWS*DIM];
__device__ __align__(256) float g_qkv [(size_t)ROWS*3*DIM];
__device__ __align__(256) float g_attn[(size_t)ROWS*DIM];
__device__ __align__(256) float g_res [(size_t)ROWS*DIM];
__device__ __align__(256) float g_out1[(size_t)ROWS*DIM];
__device__ __align__(256) float g_hid [(size_t)ROWS*4*DIM];
__device__ __align__(256) float g_wt  [25165824];   // tf32-rounded weights

// weight offsets within g_wt (per layer: qkv 3.14M, wo 1.05M, mlpa 4.19M, mlpb 4.19M)
#define OFF_QKV 0
#define OFF_WO  3145728
#define OFF_MA  4194304
#define OFF_MB  8388608
#define LAYER_W 12582912

__device__ __forceinline__ uint32_t f2tf(float f) {
    uint32_t r; asm("cvt.rna.tf32.f32 %0, %1;" : "=r"(r) : "f"(f)); return r;
}
__device__ __forceinline__ float f2tf_f(float f) {
    uint32_t r = f2tf(f); return __uint_as_float(r);
}

// ---------------- tf32 pre-round pass for weights ----------------
__global__ __launch_bounds__(256) void cvt_tf32(const float* __restrict__ s,
                                                float* __restrict__ d)
{
    int i = blockIdx.x * 256 + threadIdx.x;
    float4 v = reinterpret_cast<const float4*>(s)[i];
    v.x = f2tf_f(v.x); v.y = f2tf_f(v.y); v.z = f2tf_f(v.z); v.w = f2tf_f(v.w);
    reinterpret_cast<float4*>(d)[i] = v;
}

// ---------------- LayerNorm (outputs tf32-rounded) ----------------
__global__ __launch_bounds__(256) void ln_kernel(const float* __restrict__ x,
                                                 const float* __restrict__ g,
                                                 const float* __restrict__ b,
                                                 float* __restrict__ y)
{
    int row = blockIdx.x, t = threadIdx.x;
    float4 v = reinterpret_cast<const float4*>(x + (size_t)row * DIM)[t];
    float s = v.x + v.y + v.z + v.w;
    float q = v.x*v.x + v.y*v.y + v.z*v.z + v.w*v.w;
    #pragma unroll
    for (int o = 16; o > 0; o >>= 1) {
        s += __shfl_xor_sync(0xffffffffu, s, o);
        q += __shfl_xor_sync(0xffffffffu, q, o);
    }
    __shared__ float rs_[8], rq_[8];
    __shared__ float s_mu, s_rs;
    if ((t & 31) == 0) { rs_[t>>5] = s; rq_[t>>5] = q; }
    __syncthreads();
    if (t == 0) {
        float S = 0.f, Q = 0.f;
        #pragma unroll
        for (int i = 0; i < 8; i++) { S += rs_[i]; Q += rq_[i]; }
        float mu = S * (1.0f/DIM);
        s_mu = mu;
        s_rs = rsqrtf(Q * (1.0f/DIM) - mu*mu + 1e-5f);
    }
    __syncthreads();
    float mu = s_mu, r = s_rs;
    float4 g4 = reinterpret_cast<const float4*>(g)[t];
    float4 b4 = reinterpret_cast<const float4*>(b)[t];
    float4 o;
    o.x = f2tf_f((v.x-mu)*r*g4.x + b4.x);  o.y = f2tf_f((v.y-mu)*r*g4.y + b4.y);
    o.z = f2tf_f((v.z-mu)*r*g4.z + b4.z);  o.w = f2tf_f((v.w-mu)*r*g4.w + b4.w);
    reinterpret_cast<float4*>(y + (size_t)row * DIM)[t] = o;
}

// ---------------- TF32 GEMM (inputs pre-rounded): C = A@B + bias (+Rsd) ----------------
#define GBM 128
#define GBN 128
#define GBK 32
#define LDSP 36
// A: 2 stages x 128 rows x 32 floats (XOR-swizzled, 128B rows) = 32KB
// B: 2 stages x 128 n x 36 floats (padded)                     = 36KB
#define A_STAGE (GBM*GBK)             // floats
#define B_STAGE (GBN*LDSP)            // floats
#define GEMM_SMEM ((2*A_STAGE + 2*B_STAGE)*4)

__device__ __forceinline__ void ldsm4(uint32_t& r0, uint32_t& r1, uint32_t& r2, uint32_t& r3, uint32_t a) {
    asm volatile("ldmatrix.sync.aligned.m8n8.x4.shared.b16 {%0,%1,%2,%3}, [%4];"
                 : "=r"(r0), "=r"(r1), "=r"(r2), "=r"(r3) : "r"(a));
}
__device__ __forceinline__ void mma_tf32(float* c, const uint32_t* a, const uint32_t* b) {
    asm volatile("mma.sync.aligned.m16n8k8.row.col.f32.tf32.tf32.f32 "
                 "{%0,%1,%2,%3}, {%4,%5,%6,%7}, {%8,%9}, {%0,%1,%2,%3};"
                 : "+f"(c[0]), "+f"(c[1]), "+f"(c[2]), "+f"(c[3])
                 : "r"(a[0]), "r"(a[1]), "r"(a[2]), "r"(a[3]), "r"(b[0]), "r"(b[1]));
}
__device__ __forceinline__ void cp16(uint32_t dst, const float* src) {
    asm volatile("cp.async.cg.shared.global [%0], [%1], 16;" :: "r"(dst), "l"(src));
}

template <bool RES, bool RND>
__global__ __launch_bounds__(256, 2) void gemm_tf32(
    const float* __restrict__ A, const float* __restrict__ B,
    const float* __restrict__ bias, const float* __restrict__ Rsd,
    float* __restrict__ C, int M, int N, int K)
{
    extern __shared__ float smem[];
    float* As = smem;                       // 2 x A_STAGE
    float* Bs = smem + 2 * A_STAGE;         // 2 x B_STAGE

    const int t = threadIdx.x, lane = t & 31, warp = t >> 5;
    const int wm = warp >> 2, wn = warp & 3;
    const int bm0 = blockIdx.y * GBM, bn0 = blockIdx.x * GBN;

    // A producer (cp.async): thread t -> row t>>1, 4 chunks of 16B
    const int arow = t >> 1;
    const float* Ag = A + (size_t)(bm0 + arow) * K;
    const int axr = (arow & 7) * 16;
    // B producer (LDG + STS)
    const int bn = t & 127, bk0 = (t >> 7) * 16;
    const float* Bg = B + (size_t)bk0 * N + bn0 + bn;

    const uint32_t as_u = (uint32_t)__cvta_generic_to_shared(As);
    const uint32_t bs_u = (uint32_t)__cvta_generic_to_shared(Bs);
    const uint32_t a_dst = as_u + (uint32_t)arow * 128;

    // ldmatrix geometry
    const int lrow = (lane & 7) + ((lane >> 3) & 1) * 8;     // 0..15
    const int halfB16 = ((lane >> 4) & 1) * 16;              // byte offset within 32B k-chunk
    const int xrr = (lane & 7) * 16;
    const uint32_t a_rd = as_u + (uint32_t)((wm * 64 + lrow) * 128);
    const uint32_t b_off = (uint32_t)(((wn * 32 + lrow) * LDSP + ((lane >> 4) & 1) * 4) * 4);

    float rb[16];
    float acc[4][4][4];
    #pragma unroll
    for (int i = 0; i < 4; i++)
        #pragma unroll
        for (int j = 0; j < 4; j++)
            #pragma unroll
            for (int k = 0; k < 4; k++) acc[i][j][k] = 0.f;

    auto cpA = [&](int kt, int st) {
        uint32_t d0 = a_dst + (uint32_t)st * (A_STAGE * 4);
        const float* src = Ag + (size_t)kt * GBK;
        #pragma unroll
        for (int u = 0; u < 4; u++) {
            int c = u * 2 + (t & 1);
            cp16(d0 + (uint32_t)((c * 16) ^ axr), src + c * 4);
        }
        asm volatile("cp.async.commit_group;");
    };
    auto gloadB = [&](int kt) {
        #pragma unroll
        for (int s = 0; s < 16; s++)
            rb[s] = Bg[(size_t)(kt * GBK + s) * N];
    };
    auto sstoreB = [&](int st) {
        float* Bd = Bs + st * B_STAGE;
        #pragma unroll
        for (int s4 = 0; s4 < 4; s4++) {
            float4 u = make_float4(rb[s4*4+0], rb[s4*4+1], rb[s4*4+2], rb[s4*4+3]);
            *reinterpret_cast<float4*>(&Bd[bn * LDSP + bk0 + s4*4]) = u;
        }
    };
    auto compute = [&](int st) {
        uint32_t ab = a_rd + (uint32_t)st * (A_STAGE * 4);
        uint32_t bb = bs_u + (uint32_t)st * (B_STAGE * 4) + b_off;
        #pragma unroll
        for (int kk = 0; kk < 4; kk++) {
            uint32_t ak = (uint32_t)((kk * 32 + halfB16) ^ xrr);
            uint32_t afr[4][4];
            #pragma unroll
            for (int ms = 0; ms < 4; ms++)
                ldsm4(afr[ms][0], afr[ms][1], afr[ms][2], afr[ms][3],
                      ab + (uint32_t)(ms * 16 * 128) + ak);
            uint32_t bfr[4][2];
            #pragma unroll
            for (int p = 0; p < 2; p++) {
                uint32_t r0, r1, r2, r3;
                ldsm4(r0, r1, r2, r3, bb + (uint32_t)(p * 16 * LDSP + kk * 8) * 4);
                bfr[2*p][0] = r0; bfr[2*p][1] = r2;
                bfr[2*p+1][0] = r1; bfr[2*p+1][1] = r3;
            }
            #pragma unroll
            for (int ms = 0; ms < 4; ms++)
                #pragma unroll
                for (int nt = 0; nt < 4; nt++)
                    mma_tf32(acc[ms][nt], afr[ms], bfr[nt]);
        }
    };

    const int KT = K / GBK;
    cpA(0, 0);
    gloadB(0);
    sstoreB(0);
    asm volatile("cp.async.wait_group 0;");
    __syncthreads();
    for (int kt = 0; kt < KT; kt++) {
        if (kt + 1 < KT) { cpA(kt + 1, (kt + 1) & 1); gloadB(kt + 1); }
        compute(kt & 1);
        if (kt + 1 < KT) {
            sstoreB((kt + 1) & 1);
            asm volatile("cp.async.wait_group 0;");
            __syncthreads();
        }
    }

    #pragma unroll
    for (int ms = 0; ms < 4; ms++) {
        int r0 = bm0 + wm*64 + ms*16 + (lane >> 2);
        #pragma unroll
        for (int nt = 0; nt < 4; nt++) {
            int c0 = bn0 + wn*32 + nt*8 + (lane & 3)*2;
            float2 bv = *reinterpret_cast<const float2*>(&bias[c0]);
            float2 o0, o1;
            o0.x = acc[ms][nt][0] + bv.x;  o0.y = acc[ms][nt][1] + bv.y;
            o1.x = acc[ms][nt][2] + bv.x;  o1.y = acc[ms][nt][3] + bv.y;
            if (RES) {
                float2 v0 = *reinterpret_cast<const float2*>(&Rsd[(size_t)r0 * N + c0]);
                float2 v1 = *reinterpret_cast<const float2*>(&Rsd[(size_t)(r0+8) * N + c0]);
                o0.x += v0.x; o0.y += v0.y;  o1.x += v1.x; o1.y += v1.y;
            }
            if (RND) {
                o0.x = f2tf_f(o0.x); o0.y = f2tf_f(o0.y);
                o1.x = f2tf_f(o1.x); o1.y = f2tf_f(o1.y);
            }
            *reinterpret_cast<float2*>(&C[(size_t)r0 * N + c0]) = o0;
            *reinterpret_cast<float2*>(&C[(size_t)(r0+8) * N + c0]) = o1;
        }
    }
}

// ---------------- window attention ----------------
#define APAD 68
#define ATTN_SMEM (4*64*APAD*4)

template <bool SHIFTED>
__global__ __launch_bounds__(256) void attn_kernel(const float* __restrict__ qkv,
                                                   float* __restrict__ out)
{
    extern __shared__ float sm[];
    float* Qst = sm;                  // [d][l]
    float* Kst = Qst + 64*APAD;       // [d][l]
    float* Vs  = Kst + 64*APAD;       // [l][d]
    float* Pt  = Vs  + 64*APAD;       // [j][i]
    __shared__ int tok[64];
    __shared__ int rid[64];

    const int h  = blockIdx.x;
    const int wb = blockIdx.y;
    const int t  = threadIdx.x;
    const int b = wb >> 6, win = wb & 63;
    const int wr = win >> 3, wc = win & 7;

    if (t < 64) {
        int r = wr*8 + (t >> 3), c = wc*8 + (t & 7);
        int rr = r, cc = c;
        if (SHIFTED) { rr = (r + 4) & 63; cc = (c + 4) & 63; }
        tok[t] = b * NTOK + rr * GRID_S + cc;
        if (SHIFTED) {
            int fr = (r < 56) ? 0 : ((r < 60) ? 1 : 2);
            int fc = (c < 56) ? 0 : ((c < 60) ? 1 : 2);
            rid[t] = fr * 3 + fc;
        }
    }
    __syncthreads();

    {
        int l = t >> 2, d0 = (t & 3) * 16;
        const float* bp = qkv + (size_t)tok[l] * (3*DIM) + h * DHEAD;
        #pragma unroll
        for (int u = 0; u < 4; u++) {
            int d = d0 + u*4;
            float4 q4 = *reinterpret_cast<const float4*>(bp + d);
            float4 k4 = *reinterpret_cast<const float4*>(bp + DIM + d);
            float4 v4 = *reinterpret_cast<const float4*>(bp + 2*DIM + d);
            Qst[(d+0)*APAD + l] = q4.x; Qst[(d+1)*APAD + l] = q4.y;
            Qst[(d+2)*APAD + l] = q4.z; Qst[(d+3)*APAD + l] = q4.w;
            Kst[(d+0)*APAD + l] = k4.x; Kst[(d+1)*APAD + l] = k4.y;
            Kst[(d+2)*APAD + l] = k4.z; Kst[(d+3)*APAD + l] = k4.w;
            *reinterpret_cast<float4*>(&Vs[l*APAD + d]) = v4;
        }
    }
    __syncthreads();

    {
        int i0 = (t >> 4) * 4, j0 = (t & 15) * 4;
        float a[4][4];
        #pragma unroll
        for (int i = 0; i < 4; i++)
            #pragma unroll
            for (int j = 0; j < 4; j++) a[i][j] = 0.f;
        #pragma unroll 8
        for (int d = 0; d < 64; d++) {
            float4 qv = *reinterpret_cast<const float4*>(&Qst[d*APAD + i0]);
            float4 kv = *reinterpret_cast<const float4*>(&Kst[d*APAD + j0]);
            float qa[4] = { qv.x, qv.y, qv.z, qv.w };
            float ka[4] = { kv.x, kv.y, kv.z, kv.w };
            #pragma unroll
            for (int i = 0; i < 4; i++)
                #pragma unroll
                for (int j = 0; j < 4; j++)
                    a[i][j] = fmaf(qa[i], ka[j], a[i][j]);
        }
        #pragma unroll
        for (int jj = 0; jj < 4; jj++) {
            float4 o;
            float* op = &o.x;
            #pragma unroll
            for (int ii = 0; ii < 4; ii++) {
                float s = a[ii][jj] * 0.125f;
                if (SHIFTED && (rid[i0+ii] != rid[j0+jj])) s = -1e9f;
                op[ii] = s;
            }
            *reinterpret_cast<float4*>(&Pt[(j0+jj)*APAD + i0]) = o;
        }
    }
    __syncthreads();

    if (t < 64) {
        float m = -1e30f;
        #pragma unroll 8
        for (int j = 0; j < 64; j++) m = fmaxf(m, Pt[j*APAD + t]);
        float s = 0.f;
        #pragma unroll 8
        for (int j = 0; j < 64; j++) {
            float e = __expf(Pt[j*APAD + t] - m);
            Pt[j*APAD + t] = e;
            s += e;
        }
        float inv = 1.0f / s;
        #pragma unroll 8
        for (int j = 0; j < 64; j++) Pt[j*APAD + t] *= inv;
    }
    __syncthreads();

    {
        int i0 = (t >> 4) * 4, d0 = (t & 15) * 4;
        float a[4][4];
        #pragma unroll
        for (int i = 0; i < 4; i++)
            #pragma unroll
            for (int d = 0; d < 4; d++) a[i][d] = 0.f;
        #pragma unroll 8
        for (int j = 0; j < 64; j++) {
            float4 pv = *reinterpret_cast<const float4*>(&Pt[j*APAD + i0]);
            float4 vv = *reinterpret_cast<const float4*>(&Vs[j*APAD + d0]);
            float pa[4] = { pv.x, pv.y, pv.z, pv.w };
            float va[4] = { vv.x, vv.y, vv.z, vv.w };
            #pragma unroll
            for (int i = 0; i < 4; i++)
                #pragma unroll
                for (int d = 0; d < 4; d++)
                    a[i][d] = fmaf(pa[i], va[d], a[i][d]);
        }
        #pragma unroll
        for (int ii = 0; ii < 4; ii++) {
            float4 o = { f2tf_f(a[ii][0]), f2tf_f(a[ii][1]), f2tf_f(a[ii][2]), f2tf_f(a[ii][3]) };
            *reinterpret_cast<float4*>(&out[(size_t)tok[i0+ii]*DIM + h*DHEAD + d0]) = o;
        }
    }
}

// ---------------- host launch ----------------
static void run_gemm(const float* A, const float* B, const float* bias,
                     const float* Rsd, float* C, int M, int N, int K, bool rnd)
{
    dim3 grid(N / GBN, M / GBM);
    if (Rsd) {
        gemm_tf32<true, false><<<grid, 256, GEMM_SMEM>>>(A, B, bias, Rsd, C, M, N, K);
    } else {
        if (rnd) gemm_tf32<false, true ><<<grid, 256, GEMM_SMEM>>>(A, B, bias, nullptr, C, M, N, K);
        else     gemm_tf32<false, false><<<grid, 256, GEMM_SMEM>>>(A, B, bias, nullptr, C, M, N, K);
    }
}

extern "C" void kernel_launch(void* const* d_in, const int* in_sizes, int n_in,
                              void* d_out, int out_size)
{
    const float* x      = (const float*)d_in[0];
    const float* ln1g   = (const float*)d_in[1];
    const float* ln1b   = (const float*)d_in[2];
    const float* ln2g   = (const float*)d_in[3];
    const float* ln2b   = (const float*)d_in[4];
    const float* ln3g   = (const float*)d_in[5];
    const float* ln3b   = (const float*)d_in[6];
    const float* ln4g   = (const float*)d_in[7];
    const float* ln4b   = (const float*)d_in[8];
    const float* m1aw   = (const float*)d_in[9];
    const float* m1ab   = (const float*)d_in[10];
    const float* m2aw   = (const float*)d_in[11];
    const float* m2ab   = (const float*)d_in[12];
    const float* m1bw   = (const float*)d_in[13];
    const float* m1bb   = (const float*)d_in[14];
    const float* m2bw   = (const float*)d_in[15];
    const float* m2bb   = (const float*)d_in[16];
    const float* a1qkvw = (const float*)d_in[17];
    const float* a1qkvb = (const float*)d_in[18];
    const float* a1ow   = (const float*)d_in[19];
    const float* a1ob   = (const float*)d_in[20];
    const float* a2qkvw = (const float*)d_in[21];
    const float* a2qkvb = (const float*)d_in[22];
    const float* a2ow   = (const float*)d_in[23];
    const float* a2ob   = (const float*)d_in[24];
    float* out = (float*)d_out;

    float *nrm, *qkv, *att, *res, *out1, *hid, *wt;
    cudaGetSymbolAddress((void**)&nrm,  g_norm);
    cudaGetSymbolAddress((void**)&qkv,  g_qkv);
    cudaGetSymbolAddress((void**)&att,  g_attn);
    cudaGetSymbolAddress((void**)&res,  g_res);
    cudaGetSymbolAddress((void**)&out1, g_out1);
    cudaGetSymbolAddress((void**)&hid,  g_hid);
    cudaGetSymbolAddress((void**)&wt,   g_wt);

    cudaFuncSetAttribute(gemm_tf32<true,false>,  cudaFuncAttributeMaxDynamicSharedMemorySize, GEMM_SMEM);
    cudaFuncSetAttribute(gemm_tf32<false,true>,  cudaFuncAttributeMaxDynamicSharedMemorySize, GEMM_SMEM);
    cudaFuncSetAttribute(gemm_tf32<false,false>, cudaFuncAttributeMaxDynamicSharedMemorySize, GEMM_SMEM);
    cudaFuncSetAttribute(attn_kernel<false>, cudaFuncAttributeMaxDynamicSharedMemorySize, ATTN_SMEM);
    cudaFuncSetAttribute(attn_kernel<true>,  cudaFuncAttributeMaxDynamicSharedMemorySize, ATTN_SMEM);

    // ---- pre-round weights to tf32 (into g_wt) ----
    float* w1qkv = wt + OFF_QKV;
    float* w1o   = wt + OFF_WO;
    float* w1ma  = wt + OFF_MA;
    float* w1mb  = wt + OFF_MB;
    float* w2qkv = wt + LAYER_W + OFF_QKV;
    float* w2o   = wt + LAYER_W + OFF_WO;
    float* w2ma  = wt + LAYER_W + OFF_MA;
    float* w2mb  = wt + LAYER_W + OFF_MB;
    cvt_tf32<<<(DIM*3*DIM)/1024, 256>>>(a1qkvw, w1qkv);
    cvt_tf32<<<(DIM*DIM)/1024,   256>>>(a1ow,   w1o);
    cvt_tf32<<<(DIM*4*DIM)/1024, 256>>>(m1aw,   w1ma);
    cvt_tf32<<<(4*DIM*DIM)/1024, 256>>>(m1bw,   w1mb);
    cvt_tf32<<<(DIM*3*DIM)/1024, 256>>>(a2qkvw, w2qkv);
    cvt_tf32<<<(DIM*DIM)/1024,   256>>>(a2ow,   w2o);
    cvt_tf32<<<(DIM*4*DIM)/1024, 256>>>(m2aw,   w2ma);
    cvt_tf32<<<(4*DIM*DIM)/1024, 256>>>(m2bw,   w2mb);

    // ---- layer 1: W-MSA ----
    ln_kernel<<<ROWS, 256>>>(x, ln1g, ln1b, nrm);
    run_gemm(nrm, w1qkv, a1qkvb, nullptr, qkv, ROWS, 3*DIM, DIM, true);
    attn_kernel<false><<<dim3(NHEAD, BSZ*64), 256, ATTN_SMEM>>>(qkv, att);
    run_gemm(att, w1o, a1ob, nrm, res, ROWS, DIM, DIM, false);      // w = inp1 + attn@Wo
    // ---- layer 1: MLP ----
    ln_kernel<<<ROWS, 256>>>(res, ln2g, ln2b, nrm);
    run_gemm(nrm, w1ma, m1ab, nullptr, hid, ROWS, 4*DIM, DIM, true);
    run_gemm(hid, w1mb, m1bb, res, out1, ROWS, DIM, 4*DIM, false);
    // ---- layer 2: SW-MSA ----
    ln_kernel<<<ROWS, 256>>>(out1, ln3g, ln3b, nrm);
    run_gemm(nrm, w2qkv, a2qkvb, nullptr, qkv, ROWS, 3*DIM, DIM, true);
    attn_kernel<true><<<dim3(NHEAD, BSZ*64), 256, ATTN_SMEM>>>(qkv, att);
    run_gemm(att, w2o, a2ob, out1, res, ROWS, DIM, DIM, false);     // sw = out1 + attn@Wo
    // ---- layer 2: MLP ----
    ln_kernel<<<ROWS, 256>>>(res, ln4g, ln4b, nrm);
    run_gemm(nrm, w2ma, m2ab, nullptr, hid, ROWS, 4*DIM, DIM, true);
    run_gemm(hid, w2mb, m2bb, res, out, ROWS, DIM, 4*DIM, false);
}